// round 3
// baseline (speedup 1.0000x reference)
#include <cuda_runtime.h>
#include <cuda_bf16.h>
#include <cstdint>

#define NTAGS 128
#define BATCH 256
#define SLEN  512

// ---- packed f32x2 helpers (sm_103a) ----
__device__ __forceinline__ unsigned long long pk2(float x, float y) {
    unsigned long long r;
    asm("mov.b64 %0,{%1,%2};" : "=l"(r) : "f"(x), "f"(y));
    return r;
}
__device__ __forceinline__ void upk2(unsigned long long v, float& x, float& y) {
    asm("mov.b64 {%0,%1},%2;" : "=f"(x), "=f"(y) : "l"(v));
}
__device__ __forceinline__ unsigned long long ffma2(unsigned long long a,
                                                    unsigned long long b,
                                                    unsigned long long c) {
    unsigned long long d;
    asm("fma.rn.f32x2 %0,%1,%2,%3;" : "=l"(d) : "l"(a), "l"(b), "l"(c));
    return d;
}

__global__ void crf_zero_out(float* out) { out[0] = 0.0f; }

__global__ void __launch_bounds__(NTAGS)
crf_forward_kernel(const float* __restrict__ emissions,      // [B,S,NTAGS]
                   const void* __restrict__ tags_raw,        // [B,S] int32 OR int64
                   const unsigned char* __restrict__ mask,   // [B,S]
                   const float* __restrict__ transitions,    // [NTAGS,NTAGS]
                   float* __restrict__ out)                  // [1]
{
    const int b = blockIdx.x;
    const int j = threadIdx.x;            // tag index owned by this thread
    const int lane = j & 31;
    const int wid  = j >> 5;

    __shared__ __align__(16) float pbuf[2][NTAGS];  // double-buffered p = exp(r - cref)
    __shared__ float r0s[2];                        // double-buffered r0 broadcast
    __shared__ float red[4];                        // cross-warp reduction scratch

    // -------- tags dtype auto-detect (int64 vs int32) --------
    // int64 little-endian values in [0,128) have all-zero high words at odd
    // int32 indices. Real int32 tag data there is random in [0,128):
    // P(64 consecutive zeros) ~ 128^-64. Deterministic per input.
    const int* tg32_all = (const int*)tags_raw;
    int det = 0;
#pragma unroll
    for (int i = 0; i < 64; i++) det |= tg32_all[2 * i + 1];
    const int tstride = (det == 0) ? 2 : 1;   // int64 -> read every other word

    // ---------------- prologue: eT column j into registers ----------------
    unsigned long long col[NTAGS / 2];
#pragma unroll
    for (int k = 0; k < NTAGS / 2; k++) {
        float t0 = transitions[(2 * k)     * NTAGS + j];
        float t1 = transitions[(2 * k + 1) * NTAGS + j];
        col[k] = pk2(expf(t0), expf(t1));
    }

    // ---------------- gold score (gather-sum) ----------------
    const int*           tg = tg32_all + (size_t)b * SLEN * tstride;
    const unsigned char* mk = mask + (size_t)b * SLEN;
    const float*         em = emissions + (size_t)b * SLEN * NTAGS;

    float gold = 0.0f;
#pragma unroll
    for (int t = j; t < SLEN; t += NTAGS) {
        int   tt = tg[t * tstride];
        float m  = mk[t] ? 1.0f : 0.0f;
        gold += m * em[(size_t)t * NTAGS + tt];
        if (t + 1 < SLEN) {
            int   t2 = tg[(t + 1) * tstride];
            float m2 = mk[t + 1] ? 1.0f : 0.0f;
            gold += m2 * transitions[tt * NTAGS + t2];
        }
    }

    // ---------------- forward scan ----------------
    // invariant: alpha_j = C + r_j ; cref = r0 from previous step (one-step stale,
    // but exact: the same cref used inside exp() is the one absorbed into C)
    float r = em[j];                       // alpha0 = emissions[:,0]
    if (j == 0) r0s[0] = r;
    double C = 0.0;
    float e_next = em[NTAGS + j];          // prefetch e[t=1]
    __syncthreads();
    float cref = r0s[0];                   // exact r0 for first step

    for (int t = 1; t < SLEN; t++) {
        const int buf = t & 1;
        float p = __expf(r - cref);
        pbuf[buf][j] = p;
        if (j == 0) r0s[buf] = r;          // publish current r0 (pre-update)
        float e_cur = e_next;
        if (t + 1 < SLEN) e_next = em[(size_t)(t + 1) * NTAGS + j];
        __syncthreads();                   // single barrier per step
        float cnew = r0s[buf];

        // matvec: s_j = sum_i p[i] * eT[i][j]   (f32x2, 4 accumulators)
        const ulonglong2* pq = (const ulonglong2*)pbuf[buf];
        unsigned long long a0 = 0ull, a1 = 0ull, a2 = 0ull, a3 = 0ull;
#pragma unroll
        for (int k2 = 0; k2 < 32; k2 += 2) {
            ulonglong2 q0 = pq[k2];
            ulonglong2 q1 = pq[k2 + 1];
            a0 = ffma2(q0.x, col[2 * k2],     a0);
            a1 = ffma2(q0.y, col[2 * k2 + 1], a1);
            a2 = ffma2(q1.x, col[2 * k2 + 2], a2);
            a3 = ffma2(q1.y, col[2 * k2 + 3], a3);
        }
        float x0, y0, x1, y1, x2, y2, x3, y3;
        upk2(a0, x0, y0); upk2(a1, x1, y1);
        upk2(a2, x2, y2); upk2(a3, x3, y3);
        float s = ((x0 + x1) + (x2 + x3)) + ((y0 + y1) + (y2 + y3));

        C += (double)cref;                 // absorb offset
        r  = __logf(s) + e_cur;            // new relative alpha
        cref = cnew;                       // becomes the stale offset next step
    }

    // ---------------- partition = C + logsumexp_j(r) ----------------
    float m = r;
#pragma unroll
    for (int o = 16; o > 0; o >>= 1)
        m = fmaxf(m, __shfl_xor_sync(0xFFFFFFFFu, m, o));
    if (lane == 0) red[wid] = m;
    __syncthreads();
    m = fmaxf(fmaxf(red[0], red[1]), fmaxf(red[2], red[3]));
    __syncthreads();

    float ex = __expf(r - m);
#pragma unroll
    for (int o = 16; o > 0; o >>= 1)
        ex += __shfl_xor_sync(0xFFFFFFFFu, ex, o);
    if (lane == 0) red[wid] = ex;
    __syncthreads();
    float sumex = (red[0] + red[1]) + (red[2] + red[3]);
    __syncthreads();

    // reduce gold across block
#pragma unroll
    for (int o = 16; o > 0; o >>= 1)
        gold += __shfl_xor_sync(0xFFFFFFFFu, gold, o);
    if (lane == 0) red[wid] = gold;
    __syncthreads();
    float goldtot = (red[0] + red[1]) + (red[2] + red[3]);

    if (j == 0) {
        float part = (float)(C + (double)(m + __logf(sumex)));
        atomicAdd(out, part - goldtot);
    }
}

extern "C" void kernel_launch(void* const* d_in, const int* in_sizes, int n_in,
                              void* d_out, int out_size) {
    const float*         emissions   = (const float*)d_in[0];
    const void*          tags        = (const void*)d_in[1];
    const unsigned char* mask        = (const unsigned char*)d_in[2];
    const float*         transitions = (const float*)d_in[3];
    float*               out         = (float*)d_out;

    crf_zero_out<<<1, 1>>>(out);
    crf_forward_kernel<<<BATCH, NTAGS>>>(emissions, tags, mask, transitions, out);
}